// round 15
// baseline (speedup 1.0000x reference)
#include <cuda_runtime.h>
#include <cuda_fp16.h>
#include <math.h>
#include <stdint.h>

#define N_NODES 10000
#define N_EDGES 160000
#define E_TOT   170000
#define IN_CH   1030
#define HC      1024
#define HID     256
#define OUT_CH  49
#define M_PAD   10112
#define KP1     1056
#define KP2     1024

// ---------------- device scratch ----------------
__device__ float g_xl[(size_t)N_NODES * HC];
__device__ float g_xr[(size_t)N_NODES * HC];
__device__ float g_cls[(size_t)N_NODES * HID];
__device__ float g_bias2[2 * HC];
__device__ __align__(128) __half g_ahi[(size_t)M_PAD * KP1];
__device__ __align__(128) __half g_alo[(size_t)M_PAD * KP1];
__device__ __align__(128) __half g_bh [(size_t)2 * HC * KP1];
__device__ int g_dst[E_TOT];
__device__ int g_cnt[N_NODES];
__device__ int g_rowptr[N_NODES + 1];
__device__ int g_cursor[N_NODES];
__device__ int g_perm[E_TOT];      // stores SRC node id, ordered by dst (CSR)
__device__ int g_ei_is64;

// ---------------- asm helpers ----------------
__device__ __forceinline__ uint32_t smem_u32(const void* p) {
    uint32_t a;
    asm("{ .reg .u64 t; cvta.to.shared.u64 t, %1; cvt.u32.u64 %0, t; }" : "=r"(a) : "l"(p));
    return a;
}
__device__ __forceinline__ void cp_async16(uint32_t dst, const void* src) {
    asm volatile("cp.async.cg.shared.global [%0], [%1], 16;" :: "r"(dst), "l"(src));
}
#define CP_COMMIT() asm volatile("cp.async.commit_group;")
#define CP_WAIT0()  asm volatile("cp.async.wait_group 0;" ::: "memory")
#define CP_WAIT1()  asm volatile("cp.async.wait_group 1;" ::: "memory")

__device__ __forceinline__ void ldsm4(uint32_t* r, uint32_t addr) {
    asm volatile("ldmatrix.sync.aligned.m8n8.x4.shared.b16 {%0,%1,%2,%3}, [%4];"
        : "=r"(r[0]), "=r"(r[1]), "=r"(r[2]), "=r"(r[3]) : "r"(addr));
}
__device__ __forceinline__ void mma16816(float* c, const uint32_t* a,
                                         uint32_t b0, uint32_t b1) {
    asm volatile(
        "mma.sync.aligned.m16n8k16.row.col.f32.f16.f16.f32 "
        "{%0,%1,%2,%3}, {%4,%5,%6,%7}, {%8,%9}, {%0,%1,%2,%3};"
        : "+f"(c[0]), "+f"(c[1]), "+f"(c[2]), "+f"(c[3])
        : "r"(a[0]), "r"(a[1]), "r"(a[2]), "r"(a[3]), "r"(b0), "r"(b1));
}

// ---------------- conversions ----------------
__global__ void k_cvt_a(const float* __restrict__ A, int M_real, int K_real,
                        int K_pad, int M_use) {
    size_t idx = (size_t)blockIdx.x * blockDim.x + threadIdx.x;
    size_t tot = (size_t)M_use * K_pad;
    if (idx >= tot) return;
    int r = (int)(idx / K_pad), c = (int)(idx % K_pad);
    float x = (r < M_real && c < K_real) ? A[(size_t)r * K_real + c] : 0.f;
    __half hi = __float2half_rn(x);
    __half lo = __float2half_rn(x - __half2float(hi));
    g_ahi[idx] = hi;
    g_alo[idx] = lo;
}

__global__ void k_cvt_b2(const float* __restrict__ Bl, const float* __restrict__ Br,
                         const float* __restrict__ bl, const float* __restrict__ br,
                         int K_real, int K_pad) {
    size_t idx = (size_t)blockIdx.x * blockDim.x + threadIdx.x;
    if (idx < 2 * HC) g_bias2[idx] = (idx < HC) ? bl[idx] : br[idx - HC];
    size_t tot = (size_t)2 * HC * K_pad;
    if (idx >= tot) return;
    int n = (int)(idx / K_pad), k = (int)(idx % K_pad);
    const float* B = (n < HC) ? Bl : Br;
    int nn = (n < HC) ? n : n - HC;
    float x = (k < K_real) ? B[(size_t)k * HC + nn] : 0.f;
    g_bh[idx] = __float2half_rn(x);
}

__global__ void k_cvt_b(const float* __restrict__ B, int K_real, int N, int K_pad) {
    size_t idx = (size_t)blockIdx.x * blockDim.x + threadIdx.x;
    size_t tot = (size_t)N * K_pad;
    if (idx >= tot) return;
    int n = (int)(idx / K_pad), k = (int)(idx % K_pad);
    float x = (k < K_real) ? B[(size_t)k * N + n] : 0.f;
    g_bh[idx] = __float2half_rn(x);
}

// ---------------- mma.sync split-fp16 GEMM (2-pass) ----------------
#define ROWB   80
#define TIL    (128 * ROWB)
#define STG    (3 * TIL)
#define SMEM_MMA (2 * STG)

__device__ __forceinline__ void load_stage(uint32_t sb, int it, int tid,
                                           const __half* s0, const __half* s1,
                                           const __half* s2, int K_pad) {
    uint32_t stage = sb + (uint32_t)(it & 1) * STG;
    int k0 = it * 32;
    const __half* srcs[3] = {s0, s1, s2};
    #pragma unroll
    for (int q = 0; q < 6; q++) {
        int id = tid + q * 256;
        int t = id >> 9, r = (id >> 2) & 127, u = id & 3;
        cp_async16(stage + t * TIL + r * ROWB + u * 16,
                   srcs[t] + (size_t)r * K_pad + k0 + u * 8);
    }
    CP_COMMIT();
}

__global__ __launch_bounds__(256)
void k_mma(int c_sel, const float* __restrict__ bias,
           int M, int N_tot, int K_pad, int act) {
    extern __shared__ char sm[];
    int tid = threadIdx.x, w = tid >> 5, l = tid & 31;
    int wm = w >> 1, wn = w & 1;
    int bm = blockIdx.y * 128, bn = blockIdx.x * 128;
    uint32_t sb = smem_u32(sm);
    int q = l >> 3;

    uint32_t aoff = (uint32_t)((wm * 32 + ((q & 1) << 3) + (l & 7)) * ROWB + ((q >> 1) << 4));
    uint32_t boff = (uint32_t)((wn * 64 + ((q >> 1) << 3) + (l & 7)) * ROWB + ((q & 1) << 4));

    const __half* sA_hi = g_ahi + (size_t)bm * K_pad;
    const __half* sA_lo = g_alo + (size_t)bm * K_pad;
    const __half* sB    = g_bh  + (size_t)bn * K_pad;

    float acc[2][8][4];
    #pragma unroll
    for (int m = 0; m < 2; m++)
        #pragma unroll
        for (int n = 0; n < 8; n++)
            #pragma unroll
            for (int i = 0; i < 4; i++) acc[m][n][i] = 0.f;

    int nk = K_pad / 32;
    load_stage(sb, 0, tid, sA_hi, sA_lo, sB, K_pad);
    load_stage(sb, 1, tid, sA_hi, sA_lo, sB, K_pad);

    for (int it = 0; it < nk; it++) {
        if (it == nk - 1) { CP_WAIT0(); } else { CP_WAIT1(); }
        __syncthreads();
        uint32_t stage = sb + (uint32_t)(it & 1) * STG;
        uint32_t pAhi = stage, pAlo = stage + TIL, pB = stage + 2u * TIL;
        #pragma unroll
        for (int kc = 0; kc < 2; kc++) {
            uint32_t koff = kc * 32;
            uint32_t ah[2][4], al[2][4], b[4][4];
            ldsm4(ah[0], pAhi + aoff + koff);
            ldsm4(ah[1], pAhi + aoff + 16 * ROWB + koff);
            ldsm4(al[0], pAlo + aoff + koff);
            ldsm4(al[1], pAlo + aoff + 16 * ROWB + koff);
            #pragma unroll
            for (int p = 0; p < 4; p++)
                ldsm4(b[p], pB + boff + p * (16 * ROWB) + koff);
            #pragma unroll
            for (int n = 0; n < 8; n++) {
                uint32_t b0 = b[n >> 1][(n & 1) * 2];
                uint32_t b1 = b[n >> 1][(n & 1) * 2 + 1];
                mma16816(acc[0][n], ah[0], b0, b1);
                mma16816(acc[1][n], ah[1], b0, b1);
                mma16816(acc[0][n], al[0], b0, b1);
                mma16816(acc[1][n], al[1], b0, b1);
            }
        }
        __syncthreads();
        if (it + 2 < nk) load_stage(sb, it + 2, tid, sA_hi, sA_lo, sB, K_pad);
    }

    #pragma unroll
    for (int m = 0; m < 2; m++) {
        #pragma unroll
        for (int n = 0; n < 8; n++) {
            int cglob = bn + wn * 64 + n * 8 + (l & 3) * 2;
            float* Cp;
            int cc;
            float2 bv;
            if (c_sel == 3) {
                bool right = cglob >= HC;
                Cp = right ? g_xr : g_xl;
                cc = right ? cglob - HC : cglob;
                bv = *(const float2*)(g_bias2 + cglob);
            } else {
                Cp = g_cls;
                cc = cglob;
                bv = *(const float2*)(bias + cglob);
            }
            int stride = (c_sel == 3) ? HC : N_tot;
            int r0 = bm + wm * 32 + m * 16 + (l >> 2);
            #pragma unroll
            for (int hh = 0; hh < 2; hh++) {
                int row = r0 + hh * 8;
                if (row < M) {
                    float vx = acc[m][n][hh * 2    ] + bv.x;
                    float vy = acc[m][n][hh * 2 + 1] + bv.y;
                    if (act == 1) {
                        vx = vx > 0.f ? vx : expm1f(vx);
                        vy = vy > 0.f ? vy : expm1f(vy);
                    }
                    *(float2*)(Cp + (size_t)row * stride + cc) = make_float2(vx, vy);
                }
            }
        }
    }
}

// ---------------- edge_index dtype detection ----------------
__global__ void k_detect(const unsigned long long* __restrict__ ei64) {
    int is64 = 1;
    for (int i = 0; i < 64; i++)
        if (ei64[i] >= (1ULL << 32)) { is64 = 0; break; }
    g_ei_is64 = is64;
}

// ---------------- CSR build ----------------
__global__ void k_zero_csr() {
    int i = blockIdx.x * blockDim.x + threadIdx.x;
    if (i < N_NODES) g_cnt[i] = 0;
}

__device__ int g_srcv[E_TOT];
__global__ void k_build(const void* __restrict__ ei) {
    int i = blockIdx.x * blockDim.x + threadIdx.x;
    if (i >= E_TOT) return;
    int s, d;
    if (i < N_EDGES) {
        if (g_ei_is64) {
            const long long* p = (const long long*)ei;
            s = (int)p[i]; d = (int)p[N_EDGES + i];
        } else {
            const int* p = (const int*)ei;
            s = p[i]; d = p[N_EDGES + i];
        }
    } else {
        s = d = i - N_EDGES;
    }
    if ((unsigned)s >= N_NODES) s = 0;
    if ((unsigned)d >= N_NODES) d = 0;
    g_srcv[i] = s;
    g_dst[i] = d;
    atomicAdd(&g_cnt[d], 1);
}

__global__ void k_scan() {
    __shared__ int wsum[32];
    __shared__ int carry_s;
    int tid = threadIdx.x;
    if (tid == 0) carry_s = 0;
    __syncthreads();
    for (int base = 0; base < N_NODES; base += 1024) {
        int i = base + tid;
        int v = (i < N_NODES) ? g_cnt[i] : 0;
        int incl = v;
        int lane = tid & 31, wid = tid >> 5;
        #pragma unroll
        for (int o = 1; o < 32; o <<= 1) {
            int t = __shfl_up_sync(0xffffffffu, incl, o);
            if (lane >= o) incl += t;
        }
        if (lane == 31) wsum[wid] = incl;
        __syncthreads();
        if (wid == 0) {
            int s = wsum[lane];
            #pragma unroll
            for (int o = 1; o < 32; o <<= 1) {
                int t = __shfl_up_sync(0xffffffffu, s, o);
                if (lane >= o) s += t;
            }
            wsum[lane] = s;
        }
        __syncthreads();
        int off = (wid > 0) ? wsum[wid - 1] : 0;
        int excl = carry_s + off + incl - v;
        if (i < N_NODES) { g_rowptr[i] = excl; g_cursor[i] = excl; }
        __syncthreads();
        if (tid == 0) carry_s += wsum[31];
        __syncthreads();
    }
    if (tid == 0) g_rowptr[N_NODES] = carry_s;
}

__global__ void k_scatter() {
    int e = blockIdx.x * blockDim.x + threadIdx.x;
    if (e >= E_TOT) return;
    int pos = atomicAdd(&g_cursor[g_dst[e]], 1);
    g_perm[pos] = g_srcv[e];          // store src id directly
}

// ---- fully fused edge phase: scores + exp + aggregate + LN + ELU + fp16 split
// block per dst node, 256 threads; thread t owns channel t of each head.
#define EG 4
__global__ __launch_bounds__(256)
void k_fused(const float* __restrict__ att, const float* __restrict__ bias,
             const float* __restrict__ w, const float* __restrict__ b) {
    __shared__ float att_s[HC];
    __shared__ float red_s[8][16];     // per-warp partials (4 edges x 4 heads)
    __shared__ float p_s[16];          // exp'ed scores for the group
    __shared__ float rs[8], rs2[8];
    int n = blockIdx.x;
    int tid = threadIdx.x;
    int lane = tid & 31, wid = tid >> 5;

    float xr[4];
    #pragma unroll
    for (int i = 0; i < 4; i++) {
        xr[i] = g_xr[(size_t)n * HC + tid + i * 256];
        att_s[tid + i * 256] = att[tid + i * 256];
    }
    __syncthreads();

    float acc[4] = {0.f, 0.f, 0.f, 0.f};
    float den[4] = {0.f, 0.f, 0.f, 0.f};
    int beg = g_rowptr[n], end = g_rowptr[n + 1];

    for (int j = beg; j < end; j += EG) {
        int ne = min(EG, end - j);
        float xlv[EG][4];
        float part[EG][4];
        #pragma unroll
        for (int t = 0; t < EG; t++) {
            if (t < ne) {
                int s = g_perm[j + t];
                const float* row = g_xl + (size_t)s * HC;
                #pragma unroll
                for (int i = 0; i < 4; i++) {
                    float xv = row[tid + i * 256];
                    xlv[t][i] = xv;
                    float m = xv + xr[i];
                    m = m > 0.f ? m : 0.2f * m;
                    part[t][i] = m * att_s[tid + i * 256];
                }
            } else {
                #pragma unroll
                for (int i = 0; i < 4; i++) { xlv[t][i] = 0.f; part[t][i] = 0.f; }
            }
        }
        // warp reduce 16 values
        #pragma unroll
        for (int t = 0; t < EG; t++)
            #pragma unroll
            for (int i = 0; i < 4; i++) {
                float v = part[t][i];
                #pragma unroll
                for (int o = 16; o; o >>= 1) v += __shfl_xor_sync(0xffffffffu, v, o);
                if (lane == 0) red_s[wid][t * 4 + i] = v;
            }
        __syncthreads();
        if (tid < 16) {
            float v = 0.f;
            #pragma unroll
            for (int ww = 0; ww < 8; ww++) v += red_s[ww][tid];
            p_s[tid] = expf(v);       // softmax without max-shift (scores O(1))
        }
        __syncthreads();
        #pragma unroll
        for (int t = 0; t < EG; t++) {
            if (t < ne) {
                #pragma unroll
                for (int i = 0; i < 4; i++) {
                    float p = p_s[t * 4 + i];
                    den[i] += p;
                    acc[i] = fmaf(p, xlv[t][i], acc[i]);
                }
            }
        }
        __syncthreads();
    }

    // LayerNorm + ELU + split-fp16 write
    float v[4];
    float s = 0.f, s2 = 0.f;
    #pragma unroll
    for (int i = 0; i < 4; i++) {
        v[i] = acc[i] / (den[i] + 1e-16f) + bias[tid + i * 256];
        s += v[i];
        s2 += v[i] * v[i];
    }
    #pragma unroll
    for (int o = 16; o; o >>= 1) {
        s  += __shfl_xor_sync(0xffffffffu, s,  o);
        s2 += __shfl_xor_sync(0xffffffffu, s2, o);
    }
    if (lane == 0) { rs[wid] = s; rs2[wid] = s2; }
    __syncthreads();
    if (tid == 0) {
        float a = 0.f, a2 = 0.f;
        #pragma unroll
        for (int i = 0; i < 8; i++) { a += rs[i]; a2 += rs2[i]; }
        rs[0] = a; rs2[0] = a2;
    }
    __syncthreads();
    float mu = rs[0] * (1.f / HC);
    float var = rs2[0] * (1.f / HC) - mu * mu;
    float r = rsqrtf(var + 1e-5f);
    size_t base = (size_t)n * KP2;
    #pragma unroll
    for (int i = 0; i < 4; i++) {
        int c = tid + i * 256;
        float y = (v[i] - mu) * r * w[c] + b[c];
        y = y > 0.f ? y : expm1f(y);
        __half hi = __float2half_rn(y);
        __half lo = __float2half_rn(y - __half2float(hi));
        g_ahi[base + c] = hi;
        g_alo[base + c] = lo;
    }
}

// ---------------- classifier layer 2 ----------------
#define CLS_N   32
#define SMEM_CLS ((HID * OUT_CH + CLS_N * HID) * 4)
__global__ __launch_bounds__(256)
void k_cls2(const float* __restrict__ w2, const float* __restrict__ b2,
            float* __restrict__ out) {
    extern __shared__ float smc[];
    float* sw  = smc;
    float* shh = smc + HID * OUT_CH;
    int tid = threadIdx.x;
    int base = blockIdx.x * CLS_N;
    for (int i = tid; i < HID * OUT_CH; i += 256) sw[i] = w2[i];
    for (int i = tid; i < CLS_N * HID; i += 256) {
        int n = i >> 8, c = i & 255;
        int gn = base + n;
        shh[i] = (gn < N_NODES) ? g_cls[(size_t)gn * HID + c] : 0.f;
    }
    __syncthreads();
    int j = tid & 63, grp = tid >> 6;
    if (j < OUT_CH) {
        float bj = b2[j];
        for (int n = grp; n < CLS_N; n += 4) {
            int gn = base + n;
            if (gn >= N_NODES) break;
            const float4* hr = (const float4*)(shh + n * HID);
            float a = bj;
            #pragma unroll 16
            for (int k4 = 0; k4 < HID / 4; k4++) {
                float4 h4 = hr[k4];
                int k = k4 * 4;
                a = fmaf(h4.x, sw[(k    ) * OUT_CH + j], a);
                a = fmaf(h4.y, sw[(k + 1) * OUT_CH + j], a);
                a = fmaf(h4.z, sw[(k + 2) * OUT_CH + j], a);
                a = fmaf(h4.w, sw[(k + 3) * OUT_CH + j], a);
            }
            out[(size_t)gn * OUT_CH + j] = a;
        }
    }
}

// ---------------- launch ----------------
extern "C" void kernel_launch(void* const* d_in, const int* in_sizes, int n_in,
                              void* d_out, int out_size) {
    static const int MAP_INSERT[22] =
        {0,1,2,3,4,5,6,7,8,9,10,11,12,13,14,15,16,17,18,19,20,21};
    static const int MAP_ALPHA[22] =
        {21, 16, 4, 2, 5, 3, 0, 1, 18, 17,
         10, 8, 11, 9, 6, 7, 20, 19, 14, 12, 15, 13};
    const int* map = MAP_INSERT;
    if (n_in >= 22 && in_sizes[0] != N_NODES * IN_CH && in_sizes[21] == N_NODES * IN_CH)
        map = MAP_ALPHA;

    const float* x       = (const float*)d_in[map[0]];
    const void*  ei      = d_in[map[1]];
    const float* c1_wl   = (const float*)d_in[map[2]];
    const float* c1_bl   = (const float*)d_in[map[3]];
    const float* c1_wr   = (const float*)d_in[map[4]];
    const float* c1_br   = (const float*)d_in[map[5]];
    const float* c1_att  = (const float*)d_in[map[6]];
    const float* c1_bias = (const float*)d_in[map[7]];
    const float* ln1_w   = (const float*)d_in[map[8]];
    const float* ln1_b   = (const float*)d_in[map[9]];
    const float* c2_wl   = (const float*)d_in[map[10]];
    const float* c2_bl   = (const float*)d_in[map[11]];
    const float* c2_wr   = (const float*)d_in[map[12]];
    const float* c2_br   = (const float*)d_in[map[13]];
    const float* c2_att  = (const float*)d_in[map[14]];
    const float* c2_bias = (const float*)d_in[map[15]];
    const float* ln2_w   = (const float*)d_in[map[16]];
    const float* ln2_b   = (const float*)d_in[map[17]];
    const float* cls_w1  = (const float*)d_in[map[18]];
    const float* cls_b1  = (const float*)d_in[map[19]];
    const float* cls_w2  = (const float*)d_in[map[20]];
    const float* cls_b2  = (const float*)d_in[map[21]];
    float* out = (float*)d_out;

    cudaFuncSetAttribute(k_mma, cudaFuncAttributeMaxDynamicSharedMemorySize, SMEM_MMA);
    cudaFuncSetAttribute(k_cls2, cudaFuncAttributeMaxDynamicSharedMemorySize, SMEM_CLS);

    // CSR build
    k_detect<<<1, 1>>>((const unsigned long long*)ei);
    k_zero_csr<<<(N_NODES + 255) / 256, 256>>>();
    k_build<<<(E_TOT + 255) / 256, 256>>>(ei);
    k_scan<<<1, 1024>>>();
    k_scatter<<<(E_TOT + 255) / 256, 256>>>();

    const int CB = 256;
    size_t a1_tot = (size_t)M_PAD * KP1;
    size_t b2tot1 = (size_t)2 * HC * KP1, b2tot2 = (size_t)2 * HC * KP2;

    // ---- conv1 ----
    k_cvt_a<<<(int)((a1_tot + CB - 1) / CB), CB>>>(x, N_NODES, IN_CH, KP1, M_PAD);
    k_cvt_b2<<<(int)((b2tot1 + CB - 1) / CB), CB>>>(c1_wl, c1_wr, c1_bl, c1_br, IN_CH, KP1);
    {
        dim3 g(2 * HC / 128, (N_NODES + 127) / 128);
        k_mma<<<g, 256, SMEM_MMA>>>(3, nullptr, N_NODES, 2 * HC, KP1, 0);
    }
    k_fused<<<N_NODES, 256>>>(c1_att, c1_bias, ln1_w, ln1_b);

    // ---- conv2 ----
    k_cvt_b2<<<(int)((b2tot2 + CB - 1) / CB), CB>>>(c2_wl, c2_wr, c2_bl, c2_br, HC, KP2);
    {
        dim3 g(2 * HC / 128, (N_NODES + 127) / 128);
        k_mma<<<g, 256, SMEM_MMA>>>(3, nullptr, N_NODES, 2 * HC, KP2, 0);
    }
    k_fused<<<N_NODES, 256>>>(c2_att, c2_bias, ln2_w, ln2_b);

    // ---- classifier ----
    k_cvt_b<<<(int)(((size_t)HID * KP2 + CB - 1) / CB), CB>>>(cls_w1, HC, HID, KP2);
    {
        dim3 g(HID / 128, (N_NODES + 127) / 128);
        k_mma<<<g, 256, SMEM_MMA>>>(2, cls_b1, N_NODES, HID, KP2, 1);
    }
    k_cls2<<<(N_NODES + CLS_N - 1) / CLS_N, 256, SMEM_CLS>>>(cls_w2, cls_b2, out);
}

// round 17
// speedup vs baseline: 1.1237x; 1.1237x over previous
#include <cuda_runtime.h>
#include <cuda_fp16.h>
#include <math.h>
#include <stdint.h>

#define N_NODES 10000
#define N_EDGES 160000
#define E_TOT   170000
#define IN_CH   1030
#define HC      1024
#define HID     256
#define OUT_CH  49
#define M_PAD   10112
#define KP1     1056
#define KP2     1024

// ---------------- device scratch ----------------
__device__ float g_xl[(size_t)N_NODES * HC];
__device__ float g_xr[(size_t)N_NODES * HC];
__device__ float g_cls[(size_t)N_NODES * HID];
__device__ float g_bias2[2 * HC];
__device__ __align__(128) __half g_ahi[(size_t)M_PAD * KP1];
__device__ __align__(128) __half g_alo[(size_t)M_PAD * KP1];
__device__ __align__(128) __half g_bh [(size_t)2 * HC * KP1];
__device__ int g_dst[E_TOT];
__device__ int g_srcv[E_TOT];
__device__ int g_cnt[N_NODES];
__device__ int g_rowptr[N_NODES + 1];
__device__ int g_cursor[N_NODES];
__device__ int g_perm[E_TOT];      // CSR position j -> src node id
__device__ int g_pdst[E_TOT];      // CSR position j -> dst node id
__device__ float g_esc[E_TOT * 4]; // CSR-ordered exp'ed scores
__device__ int g_ei_is64;

// ---------------- asm helpers ----------------
__device__ __forceinline__ uint32_t smem_u32(const void* p) {
    uint32_t a;
    asm("{ .reg .u64 t; cvta.to.shared.u64 t, %1; cvt.u32.u64 %0, t; }" : "=r"(a) : "l"(p));
    return a;
}
__device__ __forceinline__ void cp_async16(uint32_t dst, const void* src) {
    asm volatile("cp.async.cg.shared.global [%0], [%1], 16;" :: "r"(dst), "l"(src));
}
#define CP_COMMIT() asm volatile("cp.async.commit_group;")
#define CP_WAIT0()  asm volatile("cp.async.wait_group 0;" ::: "memory")
#define CP_WAIT1()  asm volatile("cp.async.wait_group 1;" ::: "memory")

__device__ __forceinline__ void ldsm4(uint32_t* r, uint32_t addr) {
    asm volatile("ldmatrix.sync.aligned.m8n8.x4.shared.b16 {%0,%1,%2,%3}, [%4];"
        : "=r"(r[0]), "=r"(r[1]), "=r"(r[2]), "=r"(r[3]) : "r"(addr));
}
__device__ __forceinline__ void mma16816(float* c, const uint32_t* a,
                                         uint32_t b0, uint32_t b1) {
    asm volatile(
        "mma.sync.aligned.m16n8k16.row.col.f32.f16.f16.f32 "
        "{%0,%1,%2,%3}, {%4,%5,%6,%7}, {%8,%9}, {%0,%1,%2,%3};"
        : "+f"(c[0]), "+f"(c[1]), "+f"(c[2]), "+f"(c[3])
        : "r"(a[0]), "r"(a[1]), "r"(a[2]), "r"(a[3]), "r"(b0), "r"(b1));
}

// ---------------- conversions ----------------
__global__ void k_cvt_a(const float* __restrict__ A, int M_real, int K_real,
                        int K_pad, int M_use) {
    size_t idx = (size_t)blockIdx.x * blockDim.x + threadIdx.x;
    size_t tot = (size_t)M_use * K_pad;
    if (idx >= tot) return;
    int r = (int)(idx / K_pad), c = (int)(idx % K_pad);
    float x = (r < M_real && c < K_real) ? A[(size_t)r * K_real + c] : 0.f;
    __half hi = __float2half_rn(x);
    __half lo = __float2half_rn(x - __half2float(hi));
    g_ahi[idx] = hi;
    g_alo[idx] = lo;
}

__global__ void k_cvt_b2(const float* __restrict__ Bl, const float* __restrict__ Br,
                         const float* __restrict__ bl, const float* __restrict__ br,
                         int K_real, int K_pad) {
    size_t idx = (size_t)blockIdx.x * blockDim.x + threadIdx.x;
    if (idx < 2 * HC) g_bias2[idx] = (idx < HC) ? bl[idx] : br[idx - HC];
    size_t tot = (size_t)2 * HC * K_pad;
    if (idx >= tot) return;
    int n = (int)(idx / K_pad), k = (int)(idx % K_pad);
    const float* B = (n < HC) ? Bl : Br;
    int nn = (n < HC) ? n : n - HC;
    float x = (k < K_real) ? B[(size_t)k * HC + nn] : 0.f;
    g_bh[idx] = __float2half_rn(x);
}

__global__ void k_cvt_b(const float* __restrict__ B, int K_real, int N, int K_pad) {
    size_t idx = (size_t)blockIdx.x * blockDim.x + threadIdx.x;
    size_t tot = (size_t)N * K_pad;
    if (idx >= tot) return;
    int n = (int)(idx / K_pad), k = (int)(idx % K_pad);
    float x = (k < K_real) ? B[(size_t)k * N + n] : 0.f;
    g_bh[idx] = __float2half_rn(x);
}

// ---------------- mma.sync split-fp16 GEMM (2-pass) ----------------
#define ROWB   80
#define TIL    (128 * ROWB)
#define STG    (3 * TIL)
#define SMEM_MMA (2 * STG)

__device__ __forceinline__ void load_stage(uint32_t sb, int it, int tid,
                                           const __half* s0, const __half* s1,
                                           const __half* s2, int K_pad) {
    uint32_t stage = sb + (uint32_t)(it & 1) * STG;
    int k0 = it * 32;
    const __half* srcs[3] = {s0, s1, s2};
    #pragma unroll
    for (int q = 0; q < 6; q++) {
        int id = tid + q * 256;
        int t = id >> 9, r = (id >> 2) & 127, u = id & 3;
        cp_async16(stage + t * TIL + r * ROWB + u * 16,
                   srcs[t] + (size_t)r * K_pad + k0 + u * 8);
    }
    CP_COMMIT();
}

__global__ __launch_bounds__(256)
void k_mma(int c_sel, const float* __restrict__ bias,
           int M, int N_tot, int K_pad, int act) {
    extern __shared__ char sm[];
    int tid = threadIdx.x, w = tid >> 5, l = tid & 31;
    int wm = w >> 1, wn = w & 1;
    int bm = blockIdx.y * 128, bn = blockIdx.x * 128;
    uint32_t sb = smem_u32(sm);
    int q = l >> 3;

    uint32_t aoff = (uint32_t)((wm * 32 + ((q & 1) << 3) + (l & 7)) * ROWB + ((q >> 1) << 4));
    uint32_t boff = (uint32_t)((wn * 64 + ((q >> 1) << 3) + (l & 7)) * ROWB + ((q & 1) << 4));

    const __half* sA_hi = g_ahi + (size_t)bm * K_pad;
    const __half* sA_lo = g_alo + (size_t)bm * K_pad;
    const __half* sB    = g_bh  + (size_t)bn * K_pad;

    float acc[2][8][4];
    #pragma unroll
    for (int m = 0; m < 2; m++)
        #pragma unroll
        for (int n = 0; n < 8; n++)
            #pragma unroll
            for (int i = 0; i < 4; i++) acc[m][n][i] = 0.f;

    int nk = K_pad / 32;
    load_stage(sb, 0, tid, sA_hi, sA_lo, sB, K_pad);
    load_stage(sb, 1, tid, sA_hi, sA_lo, sB, K_pad);

    for (int it = 0; it < nk; it++) {
        if (it == nk - 1) { CP_WAIT0(); } else { CP_WAIT1(); }
        __syncthreads();
        uint32_t stage = sb + (uint32_t)(it & 1) * STG;
        uint32_t pAhi = stage, pAlo = stage + TIL, pB = stage + 2u * TIL;
        #pragma unroll
        for (int kc = 0; kc < 2; kc++) {
            uint32_t koff = kc * 32;
            uint32_t ah[2][4], al[2][4], b[4][4];
            ldsm4(ah[0], pAhi + aoff + koff);
            ldsm4(ah[1], pAhi + aoff + 16 * ROWB + koff);
            ldsm4(al[0], pAlo + aoff + koff);
            ldsm4(al[1], pAlo + aoff + 16 * ROWB + koff);
            #pragma unroll
            for (int p = 0; p < 4; p++)
                ldsm4(b[p], pB + boff + p * (16 * ROWB) + koff);
            #pragma unroll
            for (int n = 0; n < 8; n++) {
                uint32_t b0 = b[n >> 1][(n & 1) * 2];
                uint32_t b1 = b[n >> 1][(n & 1) * 2 + 1];
                mma16816(acc[0][n], ah[0], b0, b1);
                mma16816(acc[1][n], ah[1], b0, b1);
                mma16816(acc[0][n], al[0], b0, b1);
                mma16816(acc[1][n], al[1], b0, b1);
            }
        }
        __syncthreads();
        if (it + 2 < nk) load_stage(sb, it + 2, tid, sA_hi, sA_lo, sB, K_pad);
    }

    #pragma unroll
    for (int m = 0; m < 2; m++) {
        #pragma unroll
        for (int n = 0; n < 8; n++) {
            int cglob = bn + wn * 64 + n * 8 + (l & 3) * 2;
            float* Cp;
            int cc;
            float2 bv;
            if (c_sel == 3) {
                bool right = cglob >= HC;
                Cp = right ? g_xr : g_xl;
                cc = right ? cglob - HC : cglob;
                bv = *(const float2*)(g_bias2 + cglob);
            } else {
                Cp = g_cls;
                cc = cglob;
                bv = *(const float2*)(bias + cglob);
            }
            int stride = (c_sel == 3) ? HC : N_tot;
            int r0 = bm + wm * 32 + m * 16 + (l >> 2);
            #pragma unroll
            for (int hh = 0; hh < 2; hh++) {
                int row = r0 + hh * 8;
                if (row < M) {
                    float vx = acc[m][n][hh * 2    ] + bv.x;
                    float vy = acc[m][n][hh * 2 + 1] + bv.y;
                    if (act == 1) {
                        vx = vx > 0.f ? vx : expm1f(vx);
                        vy = vy > 0.f ? vy : expm1f(vy);
                    }
                    *(float2*)(Cp + (size_t)row * stride + cc) = make_float2(vx, vy);
                }
            }
        }
    }
}

// ---------------- edge_index dtype detection ----------------
__global__ void k_detect(const unsigned long long* __restrict__ ei64) {
    int is64 = 1;
    for (int i = 0; i < 64; i++)
        if (ei64[i] >= (1ULL << 32)) { is64 = 0; break; }
    g_ei_is64 = is64;
}

// ---------------- CSR build ----------------
__global__ void k_zero_csr() {
    int i = blockIdx.x * blockDim.x + threadIdx.x;
    if (i < N_NODES) g_cnt[i] = 0;
}

__global__ void k_build(const void* __restrict__ ei) {
    int i = blockIdx.x * blockDim.x + threadIdx.x;
    if (i >= E_TOT) return;
    int s, d;
    if (i < N_EDGES) {
        if (g_ei_is64) {
            const long long* p = (const long long*)ei;
            s = (int)p[i]; d = (int)p[N_EDGES + i];
        } else {
            const int* p = (const int*)ei;
            s = p[i]; d = p[N_EDGES + i];
        }
    } else {
        s = d = i - N_EDGES;
    }
    if ((unsigned)s >= N_NODES) s = 0;
    if ((unsigned)d >= N_NODES) d = 0;
    g_srcv[i] = s;
    g_dst[i] = d;
    atomicAdd(&g_cnt[d], 1);
}

__global__ void k_scan() {
    __shared__ int wsum[32];
    __shared__ int carry_s;
    int tid = threadIdx.x;
    if (tid == 0) carry_s = 0;
    __syncthreads();
    for (int base = 0; base < N_NODES; base += 1024) {
        int i = base + tid;
        int v = (i < N_NODES) ? g_cnt[i] : 0;
        int incl = v;
        int lane = tid & 31, wid = tid >> 5;
        #pragma unroll
        for (int o = 1; o < 32; o <<= 1) {
            int t = __shfl_up_sync(0xffffffffu, incl, o);
            if (lane >= o) incl += t;
        }
        if (lane == 31) wsum[wid] = incl;
        __syncthreads();
        if (wid == 0) {
            int s = wsum[lane];
            #pragma unroll
            for (int o = 1; o < 32; o <<= 1) {
                int t = __shfl_up_sync(0xffffffffu, s, o);
                if (lane >= o) s += t;
            }
            wsum[lane] = s;
        }
        __syncthreads();
        int off = (wid > 0) ? wsum[wid - 1] : 0;
        int excl = carry_s + off + incl - v;
        if (i < N_NODES) { g_rowptr[i] = excl; g_cursor[i] = excl; }
        __syncthreads();
        if (tid == 0) carry_s += wsum[31];
        __syncthreads();
    }
    if (tid == 0) g_rowptr[N_NODES] = carry_s;
}

__global__ void k_scatter() {
    int e = blockIdx.x * blockDim.x + threadIdx.x;
    if (e >= E_TOT) return;
    int d = g_dst[e];
    int pos = atomicAdd(&g_cursor[d], 1);
    g_perm[pos] = g_srcv[e];
    g_pdst[pos] = d;
}

// ---------------- edge scores in CSR order (dst-sorted) + fused exp --------
__global__ void k_edge_scores(const float* __restrict__ att) {
    int j = (blockIdx.x * blockDim.x + threadIdx.x) >> 5;   // CSR position
    int lane = threadIdx.x & 31;
    if (j >= E_TOT) return;
    int se = g_perm[j], de = g_pdst[j];
    const float4* pl = (const float4*)(g_xl + (size_t)se * HC);
    const float4* pr = (const float4*)(g_xr + (size_t)de * HC);  // hot in L1/L2 (dst-sorted)
    const float4* pa = (const float4*)att;
    float acc[4] = {0.f, 0.f, 0.f, 0.f};
    #pragma unroll
    for (int i = 0; i < 8; i++) {
        int idx = i * 32 + lane;
        float4 a = pl[idx], b = pr[idx], t = pa[idx];
        float mx = a.x + b.x, my = a.y + b.y, mz = a.z + b.z, mw = a.w + b.w;
        mx = mx > 0.f ? mx : 0.2f * mx;
        my = my > 0.f ? my : 0.2f * my;
        mz = mz > 0.f ? mz : 0.2f * mz;
        mw = mw > 0.f ? mw : 0.2f * mw;
        acc[i >> 1] += mx * t.x + my * t.y + mz * t.z + mw * t.w;
    }
    #pragma unroll
    for (int h = 0; h < 4; h++) {
        float v = acc[h];
        #pragma unroll
        for (int o = 16; o; o >>= 1) v += __shfl_xor_sync(0xffffffffu, v, o);
        if (lane == 0) g_esc[j * 4 + h] = expf(v);   // softmax shift-invariant, scores O(1)
    }
}

// ---- aggregation (CSR, 2-edge unrolled) + LN + ELU + split-fp16 write ----
__global__ __launch_bounds__(256)
void k_agg_ln(const float* __restrict__ bias,
              const float* __restrict__ w, const float* __restrict__ b) {
    int n = blockIdx.x;
    int tid = threadIdx.x;
    float acc0[4] = {0.f, 0.f, 0.f, 0.f}, acc1[4] = {0.f, 0.f, 0.f, 0.f};
    float den0[4] = {0.f, 0.f, 0.f, 0.f}, den1[4] = {0.f, 0.f, 0.f, 0.f};
    int beg = g_rowptr[n], end = g_rowptr[n + 1];
    int j = beg;
    for (; j + 1 < end; j += 2) {
        int s0 = g_perm[j], s1 = g_perm[j + 1];
        float4 p0 = *(const float4*)&g_esc[j * 4];
        float4 p1 = *(const float4*)&g_esc[(j + 1) * 4];
        const float* r0 = g_xl + (size_t)s0 * HC;
        const float* r1 = g_xl + (size_t)s1 * HC;
        den0[0] += p0.x; den0[1] += p0.y; den0[2] += p0.z; den0[3] += p0.w;
        den1[0] += p1.x; den1[1] += p1.y; den1[2] += p1.z; den1[3] += p1.w;
        acc0[0] = fmaf(p0.x, r0[tid      ], acc0[0]);
        acc1[0] = fmaf(p1.x, r1[tid      ], acc1[0]);
        acc0[1] = fmaf(p0.y, r0[tid + 256], acc0[1]);
        acc1[1] = fmaf(p1.y, r1[tid + 256], acc1[1]);
        acc0[2] = fmaf(p0.z, r0[tid + 512], acc0[2]);
        acc1[2] = fmaf(p1.z, r1[tid + 512], acc1[2]);
        acc0[3] = fmaf(p0.w, r0[tid + 768], acc0[3]);
        acc1[3] = fmaf(p1.w, r1[tid + 768], acc1[3]);
    }
    if (j < end) {
        int s0 = g_perm[j];
        float4 p0 = *(const float4*)&g_esc[j * 4];
        const float* r0 = g_xl + (size_t)s0 * HC;
        den0[0] += p0.x; den0[1] += p0.y; den0[2] += p0.z; den0[3] += p0.w;
        acc0[0] = fmaf(p0.x, r0[tid      ], acc0[0]);
        acc0[1] = fmaf(p0.y, r0[tid + 256], acc0[1]);
        acc0[2] = fmaf(p0.z, r0[tid + 512], acc0[2]);
        acc0[3] = fmaf(p0.w, r0[tid + 768], acc0[3]);
    }
    float v[4];
    float s = 0.f, s2 = 0.f;
    #pragma unroll
    for (int i = 0; i < 4; i++) {
        v[i] = (acc0[i] + acc1[i]) / (den0[i] + den1[i] + 1e-16f) + bias[tid + i * 256];
        s += v[i];
        s2 += v[i] * v[i];
    }
    __shared__ float rs[8], rs2[8];
    int lane = tid & 31, wid = tid >> 5;
    #pragma unroll
    for (int o = 16; o; o >>= 1) {
        s  += __shfl_xor_sync(0xffffffffu, s,  o);
        s2 += __shfl_xor_sync(0xffffffffu, s2, o);
    }
    if (lane == 0) { rs[wid] = s; rs2[wid] = s2; }
    __syncthreads();
    if (tid == 0) {
        float a = 0.f, a2 = 0.f;
        #pragma unroll
        for (int i = 0; i < 8; i++) { a += rs[i]; a2 += rs2[i]; }
        rs[0] = a; rs2[0] = a2;
    }
    __syncthreads();
    float mu = rs[0] * (1.f / HC);
    float var = rs2[0] * (1.f / HC) - mu * mu;
    float r = rsqrtf(var + 1e-5f);
    size_t base = (size_t)n * KP2;
    #pragma unroll
    for (int i = 0; i < 4; i++) {
        int c = tid + i * 256;
        float y = (v[i] - mu) * r * w[c] + b[c];
        y = y > 0.f ? y : expm1f(y);
        __half hi = __float2half_rn(y);
        __half lo = __float2half_rn(y - __half2float(hi));
        g_ahi[base + c] = hi;
        g_alo[base + c] = lo;
    }
}

// ---------------- classifier layer 2 ----------------
#define CLS_N   32
#define SMEM_CLS ((HID * OUT_CH + CLS_N * HID) * 4)
__global__ __launch_bounds__(256)
void k_cls2(const float* __restrict__ w2, const float* __restrict__ b2,
            float* __restrict__ out) {
    extern __shared__ float smc[];
    float* sw  = smc;
    float* shh = smc + HID * OUT_CH;
    int tid = threadIdx.x;
    int base = blockIdx.x * CLS_N;
    for (int i = tid; i < HID * OUT_CH; i += 256) sw[i] = w2[i];
    for (int i = tid; i < CLS_N * HID; i += 256) {
        int n = i >> 8, c = i & 255;
        int gn = base + n;
        shh[i] = (gn < N_NODES) ? g_cls[(size_t)gn * HID + c] : 0.f;
    }
    __syncthreads();
    int j = tid & 63, grp = tid >> 6;
    if (j < OUT_CH) {
        float bj = b2[j];
        for (int n = grp; n < CLS_N; n += 4) {
            int gn = base + n;
            if (gn >= N_NODES) break;
            const float4* hr = (const float4*)(shh + n * HID);
            float a = bj;
            #pragma unroll 16
            for (int k4 = 0; k4 < HID / 4; k4++) {
                float4 h4 = hr[k4];
                int k = k4 * 4;
                a = fmaf(h4.x, sw[(k    ) * OUT_CH + j], a);
                a = fmaf(h4.y, sw[(k + 1) * OUT_CH + j], a);
                a = fmaf(h4.z, sw[(k + 2) * OUT_CH + j], a);
                a = fmaf(h4.w, sw[(k + 3) * OUT_CH + j], a);
            }
            out[(size_t)gn * OUT_CH + j] = a;
        }
    }
}

// ---------------- launch ----------------
extern "C" void kernel_launch(void* const* d_in, const int* in_sizes, int n_in,
                              void* d_out, int out_size) {
    static const int MAP_INSERT[22] =
        {0,1,2,3,4,5,6,7,8,9,10,11,12,13,14,15,16,17,18,19,20,21};
    static const int MAP_ALPHA[22] =
        {21, 16, 4, 2, 5, 3, 0, 1, 18, 17,
         10, 8, 11, 9, 6, 7, 20, 19, 14, 12, 15, 13};
    const int* map = MAP_INSERT;
    if (n_in >= 22 && in_sizes[0] != N_NODES * IN_CH && in_sizes[21] == N_NODES * IN_CH)
        map = MAP_ALPHA;

    const float* x       = (const float*)d_in[map[0]];
    const void*  ei      = d_in[map[1]];
    const float* c1_wl   = (const float*)d_in[map[2]];
    const float* c1_bl   = (const float*)d_in[map[3]];
    const float* c1_wr   = (const float*)d_in[map[4]];
    const float* c1_br   = (const float*)d_in[map[5]];
    const float* c1_att  = (const float*)d_in[map[6]];
    const float* c1_bias = (const float*)d_in[map[7]];
    const float* ln1_w   = (const float*)d_in[map[8]];
    const float* ln1_b   = (const float*)d_in[map[9]];
    const float* c2_wl   = (const float*)d_in[map[10]];
    const float* c2_bl   = (const float*)d_in[map[11]];
    const float* c2_wr   = (const float*)d_in[map[12]];
    const float* c2_br   = (const float*)d_in[map[13]];
    const float* c2_att  = (const float*)d_in[map[14]];
    const float* c2_bias = (const float*)d_in[map[15]];
    const float* ln2_w   = (const float*)d_in[map[16]];
    const float* ln2_b   = (const float*)d_in[map[17]];
    const float* cls_w1  = (const float*)d_in[map[18]];
    const float* cls_b1  = (const float*)d_in[map[19]];
    const float* cls_w2  = (const float*)d_in[map[20]];
    const float* cls_b2  = (const float*)d_in[map[21]];
    float* out = (float*)d_out;

    cudaFuncSetAttribute(k_mma, cudaFuncAttributeMaxDynamicSharedMemorySize, SMEM_MMA);
    cudaFuncSetAttribute(k_cls2, cudaFuncAttributeMaxDynamicSharedMemorySize, SMEM_CLS);

    // CSR build
    k_detect<<<1, 1>>>((const unsigned long long*)ei);
    k_zero_csr<<<(N_NODES + 255) / 256, 256>>>();
    k_build<<<(E_TOT + 255) / 256, 256>>>(ei);
    k_scan<<<1, 1024>>>();
    k_scatter<<<(E_TOT + 255) / 256, 256>>>();

    int eb = (E_TOT + 7) / 8;
    const int CB = 256;
    size_t a1_tot = (size_t)M_PAD * KP1;
    size_t b2tot1 = (size_t)2 * HC * KP1, b2tot2 = (size_t)2 * HC * KP2;

    // ---- conv1 ----
    k_cvt_a<<<(int)((a1_tot + CB - 1) / CB), CB>>>(x, N_NODES, IN_CH, KP1, M_PAD);
    k_cvt_b2<<<(int)((b2tot1 + CB - 1) / CB), CB>>>(c1_wl, c1_wr, c1_bl, c1_br, IN_CH, KP1);
    {
        dim3 g(2 * HC / 128, (N_NODES + 127) / 128);
        k_mma<<<g, 256, SMEM_MMA>>>(3, nullptr, N_NODES, 2 * HC, KP1, 0);
    }
    k_edge_scores<<<eb, 256>>>(c1_att);
    k_agg_ln<<<N_NODES, 256>>>(c1_bias, ln1_w, ln1_b);

    // ---- conv2 ----
    k_cvt_b2<<<(int)((b2tot2 + CB - 1) / CB), CB>>>(c2_wl, c2_wr, c2_bl, c2_br, HC, KP2);
    {
        dim3 g(2 * HC / 128, (N_NODES + 127) / 128);
        k_mma<<<g, 256, SMEM_MMA>>>(3, nullptr, N_NODES, 2 * HC, KP2, 0);
    }
    k_edge_scores<<<eb, 256>>>(c2_att);
    k_agg_ln<<<N_NODES, 256>>>(c2_bias, ln2_w, ln2_b);

    // ---- classifier ----
    k_cvt_b<<<(int)(((size_t)HID * KP2 + CB - 1) / CB), CB>>>(cls_w1, HC, HID, KP2);
    {
        dim3 g(HID / 128, (N_NODES + 127) / 128);
        k_mma<<<g, 256, SMEM_MMA>>>(2, cls_b1, N_NODES, HID, KP2, 1);
    }
    k_cls2<<<(N_NODES + CLS_N - 1) / CLS_N, 256, SMEM_CLS>>>(cls_w2, cls_b2, out);
}